// round 9
// baseline (speedup 1.0000x reference)
#include <cuda_runtime.h>
#include <cuda_fp16.h>

// ---------------- problem constants ----------------
#define V_N   7
#define NB    256
#define KTOT  16384      // C*T
#define OE    256
#define MTOT  1792       // NB * V_N
#define H_NSTR 114688    // C*T*V
#define H_CSTR 448       // T*V

// ---------------- GEMM tiling ----------------
#define MT    112        // M rows per CTA (= 16 batch rows exactly)
#define NPB   16         // batch rows per M-block
#define KTILE 64
#define NKT_TOTAL 256    // KTOT / KTILE
#define MAXSPLIT 10
#define NCTA  148

// SMEM stage layout
#define AS_NSTR 456                   // floats per n row (448 data + 8 pad)
#define AS_BYTES (NPB * AS_NSTR * 4)  // 29184
#define B_BYTES  (KTILE * OE * 2)     // 32768 (fp16)
#define STAGE_B  (AS_BYTES + B_BYTES) // 61952
#define NSTAGE   3
#define SMEM_BYTES (NSTAGE * STAGE_B) // 185856

// ---------------- device scratch ----------------
__device__ __half g_Wh[KTOT * OE];               // fp16 fragment/swizzled W^T (8.4 MB)
__device__ float  g_part[MAXSPLIT * MTOT * OE];  // K-split partial Wh
__device__ float  g_adjn[49];
__device__ unsigned g_sync;                      // monotonic grid-barrier counter

// ---------------- helpers ----------------
__device__ __forceinline__ unsigned smem_u32(const void* p) {
    unsigned a;
    asm("{ .reg .u64 t; cvta.to.shared.u64 t, %1; cvt.u32.u64 %0, t; }" : "=r"(a) : "l"(p));
    return a;
}
__device__ __forceinline__ unsigned pk2h(float lo, float hi) {
    unsigned r;
    asm("cvt.rn.f16x2.f32 %0, %1, %2;" : "=r"(r) : "f"(hi), "f"(lo));
    return r;
}
#define CP_ASYNC_16(dst_u32, src) \
    asm volatile("cp.async.cg.shared.global [%0], [%1], 16;" :: "r"(dst_u32), "l"(src) : "memory")
#define CP_COMMIT() asm volatile("cp.async.commit_group;" ::: "memory")
#define CP_WAIT1()  asm volatile("cp.async.wait_group 1;" ::: "memory")

#define MMA_F16(c, A, B0, B1) \
    asm volatile("mma.sync.aligned.m16n8k16.row.col.f32.f16.f16.f32 " \
                 "{%0,%1,%2,%3},{%4,%5,%6,%7},{%8,%9},{%0,%1,%2,%3};\n" \
                 : "+f"(c[0]), "+f"(c[1]), "+f"(c[2]), "+f"(c[3]) \
                 : "r"(A[0]), "r"(A[1]), "r"(A[2]), "r"(A[3]), "r"(B0), "r"(B1))

// Software grid barrier. Safe: grid=148 <= SMs, 1 CTA/SM (smem), all resident.
// Monotonic counter + epoch rounding -> correct across any number of launches.
__device__ __forceinline__ void grid_sync(int tid) {
    __threadfence();
    __syncthreads();
    if (tid == 0) {
        unsigned old = atomicAdd(&g_sync, 1u);
        unsigned target = (old / NCTA + 1u) * NCTA;
        for (;;) {
            unsigned v;
            asm volatile("ld.global.acquire.gpu.u32 %0, [%1];" : "=r"(v) : "l"(&g_sync));
            if (v >= target) break;
            __nanosleep(64);
        }
    }
    __syncthreads();
}

// ================= fused kernel: prep -> barrier -> GEMM -> barrier -> tail =============
__global__ void __launch_bounds__(512, 1) fused_kernel(const float* __restrict__ h,
                                                       const float* __restrict__ W,
                                                       const float* __restrict__ a,
                                                       const float* __restrict__ Bp,
                                                       float* __restrict__ out) {
    extern __shared__ float sm[];
    const unsigned smem_base = smem_u32(sm);
    const int tid = threadIdx.x;
    const int bid = blockIdx.x;

    // ================= Phase 0: prep W -> g_Wh (fp16 frag/swizzled) =================
    // Task (tile, c): load column c of all 32 rows of k32-tile (32 coalesced 4B loads),
    // pack 16 u32, store 4 contiguous uint4 (granules c*4 + 0..3).
    {
        const int gtid = bid * 512 + tid;        // 75776 threads, 131072 tasks
#pragma unroll
        for (int i = 0; i < 2; i++) {
            int id = gtid + i * 75776;
            if (id < 131072) {
                int tile = id >> 8, c = id & 255;
                const float* wp = W + (size_t)tile * 32 * OE + c;
                unsigned pk[16];
#pragma unroll
                for (int t4 = 0; t4 < 4; t4++) {
                    float v0 = wp[(2 * t4 + 0)  * OE], v1 = wp[(2 * t4 + 1)  * OE];
                    float v2 = wp[(2 * t4 + 8)  * OE], v3 = wp[(2 * t4 + 9)  * OE];
                    float v4 = wp[(2 * t4 + 16) * OE], v5 = wp[(2 * t4 + 17) * OE];
                    float v6 = wp[(2 * t4 + 24) * OE], v7 = wp[(2 * t4 + 25) * OE];
                    unsigned p00 = pk2h(v0, v1), p01 = pk2h(v2, v3);
                    unsigned p10 = pk2h(v4, v5), p11 = pk2h(v6, v7);
                    if ((c >> 1) & 1) {
                        pk[t4 * 4 + 0] = p10; pk[t4 * 4 + 1] = p11;
                        pk[t4 * 4 + 2] = p00; pk[t4 * 4 + 3] = p01;
                    } else {
                        pk[t4 * 4 + 0] = p00; pk[t4 * 4 + 1] = p01;
                        pk[t4 * 4 + 2] = p10; pk[t4 * 4 + 3] = p11;
                    }
                }
                uint4* dst = (uint4*)g_Wh + (size_t)tile * 1024 + c * 4;
                dst[0] = make_uint4(pk[0],  pk[1],  pk[2],  pk[3]);
                dst[1] = make_uint4(pk[4],  pk[5],  pk[6],  pk[7]);
                dst[2] = make_uint4(pk[8],  pk[9],  pk[10], pk[11]);
                dst[3] = make_uint4(pk[12], pk[13], pk[14], pk[15]);
            }
        }
        if (bid == 0 && tid == 0) {
            float adj[49];
            float mn = 1e30f, mx = -1e30f;
            for (int k = 0; k < 49; k++) {
                float x = Bp[k] + 1e-6f + ((k / 7) == (k % 7) ? 1.0f : 0.0f);
                adj[k] = x;
                mn = fminf(mn, x);
                mx = fmaxf(mx, x);
            }
            float inv = 1.0f / (mx - mn);
            float dsum[7];
            for (int i2 = 0; i2 < 7; i2++) {
                float sum = 0.0f;
                for (int j = 0; j < 7; j++) {
                    adj[i2 * 7 + j] = (adj[i2 * 7 + j] - mn) * inv;
                    sum += adj[i2 * 7 + j];
                }
                dsum[i2] = sum;
            }
            for (int i2 = 0; i2 < 7; i2++) {
                float di = 1.0f / sqrtf(dsum[i2]);
                for (int j = 0; j < 7; j++)
                    g_adjn[i2 * 7 + j] = adj[i2 * 7 + j] * di / sqrtf(dsum[j]);
            }
        }
    }
    grid_sync(tid);

    // ================= Phase 1: GEMM partial Wh = hf @ W (fp16 mma.sync) =============
    {
        int mb, sp, s_cnt;
        if (bid < 40) { mb = bid / 10; sp = bid - mb * 10; s_cnt = 10; }
        else { int r = bid - 40; mb = 4 + r / 9; sp = r - (mb - 4) * 9; s_cnt = 9; }
        const int base_t = NKT_TOTAL / s_cnt, rem = NKT_TOTAL % s_cnt;
        const int cnt   = base_t + (sp < rem ? 1 : 0);
        const int start = sp * base_t + (sp < rem ? sp : rem);
        const int m0 = mb * MT;
        const int n_first = mb * NPB;

        // staging slots: 1792 A float4 + 2048 B 16B-chunks = 3840
        int srcOff[8]; unsigned dstOff[8];
        bool isB[8], valid[8];
#pragma unroll
        for (int q = 0; q < 8; q++) {
            int f = tid + q * 512;
            valid[q] = (f < 3840);
            if (f < 1792) {
                int nr = f / 112, s4 = f - nr * 112;
                isB[q] = false;
                srcOff[q] = (n_first + nr) * H_NSTR + s4 * 4;
                dstOff[q] = (unsigned)(nr * AS_NSTR * 4 + s4 * 16);
            } else {
                int b = f - 1792;
                isB[q] = true;
                srcOff[q] = b * 8;
                dstOff[q] = (unsigned)(AS_BYTES + b * 16);
            }
        }

        // fragment geometry
        const int w = tid >> 5, lane = tid & 31;
        const int g = lane >> 2, t4 = lane & 3;
        const int nu = (w < 12) ? 2 : 1;
        const int un = w & 3;
        int um[2]; int baseA[2][2];
#pragma unroll
        for (int ui = 0; ui < 2; ui++) {
            int u = (ui == 0) ? w : (w + 16);
            um[ui] = u >> 2;
#pragma unroll
            for (int r = 0; r < 2; r++) {
                int m = um[ui] * 16 + g + r * 8;
                int nr = m / 7;
                baseA[ui][r] = nr * AS_NSTR + (m - nr * 7);
            }
        }
        const int xg = (g >> 1) & 1;
        const unsigned bThread = (unsigned)((un * 64 + g) * 64);

        float acc[2][8][4];
#pragma unroll
        for (int ui = 0; ui < 2; ui++)
#pragma unroll
            for (int nt = 0; nt < 8; nt++)
#pragma unroll
                for (int r = 0; r < 4; r++) acc[ui][nt][r] = 0.0f;

        auto issue = [&](int it, int buf) {
            const int kt = start + it;
            const unsigned sb = smem_base + (unsigned)(buf * STAGE_B);
            const float* ha = h + kt * H_CSTR;
            const __half* wb = g_Wh + (size_t)kt * 16384;
#pragma unroll
            for (int q = 0; q < 8; q++) {
                if (!valid[q]) continue;
                if (isB[q]) CP_ASYNC_16(sb + dstOff[q], wb + srcOff[q]);
                else        CP_ASYNC_16(sb + dstOff[q], ha + srcOff[q]);
            }
        };

        issue(0, 0); CP_COMMIT();
        issue(1, 1); CP_COMMIT();

        int buf = 0, buf2 = 2;
        for (int it = 0; it < cnt; ++it) {
            CP_WAIT1();
            __syncthreads();
            if (it + 2 < cnt) issue(it + 2, buf2);
            CP_COMMIT();

            const float* As = sm + buf * (STAGE_B / 4);
            const char*  Bs = (const char*)sm + buf * STAGE_B + AS_BYTES;

#pragma unroll
            for (int kg = 0; kg < 4; kg++) {
                const int ko = (kg * 16 + 2 * t4) * 7;
                unsigned afr[2][4];
                afr[0][0] = pk2h(As[baseA[0][0] + ko],      As[baseA[0][0] + ko + 7]);
                afr[0][1] = pk2h(As[baseA[0][1] + ko],      As[baseA[0][1] + ko + 7]);
                afr[0][2] = pk2h(As[baseA[0][0] + ko + 56], As[baseA[0][0] + ko + 63]);
                afr[0][3] = pk2h(As[baseA[0][1] + ko + 56], As[baseA[0][1] + ko + 63]);
                if (nu == 2) {
                    afr[1][0] = pk2h(As[baseA[1][0] + ko],      As[baseA[1][0] + ko + 7]);
                    afr[1][1] = pk2h(As[baseA[1][1] + ko],      As[baseA[1][1] + ko + 7]);
                    afr[1][2] = pk2h(As[baseA[1][0] + ko + 56], As[baseA[1][0] + ko + 63]);
                    afr[1][3] = pk2h(As[baseA[1][1] + ko + 56], As[baseA[1][1] + ko + 63]);
                }
                const char* bbase = Bs + (kg >> 1) * 16384 +
                                    (unsigned)((((2 * t4 + (kg & 1)) ^ xg)) * 8) + bThread;
#pragma unroll
                for (int nt = 0; nt < 8; nt++) {
                    uint2 b = *(const uint2*)(bbase + nt * 512);
                    MMA_F16(acc[0][nt], afr[0], b.x, b.y);
                    if (nu == 2) MMA_F16(acc[1][nt], afr[1], b.x, b.y);
                }
            }
            buf = (buf == 2) ? 0 : buf + 1;
            buf2 = (buf2 == 2) ? 0 : buf2 + 1;
        }

        // epilogue: write partials
        float* op = g_part + ((size_t)sp * MTOT + m0) * OE;
#pragma unroll
        for (int ui = 0; ui < 2; ui++) {
            if (ui >= nu) break;
#pragma unroll
            for (int nt = 0; nt < 8; nt++) {
                int r = um[ui] * 16 + g;
                int c = un * 64 + nt * 8 + 2 * t4;
                *(float2*)&op[(size_t)r * OE + c]       = make_float2(acc[ui][nt][0], acc[ui][nt][1]);
                *(float2*)&op[(size_t)(r + 8) * OE + c] = make_float2(acc[ui][nt][2], acc[ui][nt][3]);
            }
        }
    }
    grid_sync(tid);

    // ================= Phase 2: tail (reduce partials, attention, elu) =================
    {
        float* red1   = sm;          // 56
        float* red2   = sm + 64;     // 56
        float* s1s    = sm + 128;    // 7
        float* s2s    = sm + 136;    // 7
        float* adjn_s = sm + 144;    // 49
        float* att    = sm + 200;    // 49
        float* att2   = sm + 256;    // 49

        const int o = tid;
        const int wid = o >> 5, lane = o & 31;

#pragma unroll 1
        for (int pass = 0; pass < 2; pass++) {
            const int n = bid + pass * NCTA;
            const bool act = (n < NB) && (tid < 256);
            __syncthreads();

            float wh[7];
            float a1 = 0.0f, a2 = 0.0f;
            if (act) {
                const int s_cnt2 = ((n >> 4) < 4) ? 10 : 9;
#pragma unroll
                for (int v = 0; v < 7; v++) {
                    float s = 0.0f;
                    for (int ksi = 0; ksi < s_cnt2; ksi++)
                        s += __ldcg(&g_part[((size_t)ksi * MTOT + n * 7 + v) * OE + o]);
                    wh[v] = s;
                }
                if (o < 49) adjn_s[o] = __ldcg(&g_adjn[o]);
                a1 = __ldg(&a[o]);
                a2 = __ldg(&a[OE + o]);
#pragma unroll
                for (int v = 0; v < 7; v++) {
                    float p1 = wh[v] * a1;
                    float p2 = wh[v] * a2;
#pragma unroll
                    for (int off = 16; off > 0; off >>= 1) {
                        p1 += __shfl_down_sync(0xffffffffu, p1, off);
                        p2 += __shfl_down_sync(0xffffffffu, p2, off);
                    }
                    if (lane == 0) { red1[wid * 7 + v] = p1; red2[wid * 7 + v] = p2; }
                }
            }
            __syncthreads();
            if (act) {
                if (o < 7) {
                    float s = 0.0f;
                    for (int w2 = 0; w2 < 8; w2++) s += red1[w2 * 7 + o];
                    s1s[o] = s;
                } else if (o >= 32 && o < 39) {
                    float s = 0.0f;
                    for (int w2 = 0; w2 < 8; w2++) s += red2[w2 * 7 + (o - 32)];
                    s2s[o - 32] = s;
                }
            }
            __syncthreads();
            if (act && o < 7) {
                float e[7];
                float mx = -1e30f;
#pragma unroll
                for (int j = 0; j < 7; j++) {
                    float x = s1s[o] + s2s[j];
                    x = (x >= 0.0f) ? x : 0.2f * x;   // leaky_relu alpha=0.2
                    e[j] = x;
                    mx = fmaxf(mx, x);
                }
                float sum = 0.0f;
#pragma unroll
                for (int j = 0; j < 7; j++) { e[j] = expf(e[j] - mx); sum += e[j]; }
                float inv = 1.0f / sum;
#pragma unroll
                for (int j = 0; j < 7; j++) att[o * 7 + j] = e[j] * inv;
            }
            __syncthreads();
            if (act && o < 49) {
                int i = o / 7, kcol = o - i * 7;
                float s = 0.0f;
#pragma unroll
                for (int j = 0; j < 7; j++) s += adjn_s[i * 7 + j] * att[j * 7 + kcol];
                att2[o] = s;
            }
            __syncthreads();
            if (act) {
#pragma unroll
                for (int v = 0; v < 7; v++) {
                    float s = 0.0f;
#pragma unroll
                    for (int j = 0; j < 7; j++) s += att2[v * 7 + j] * wh[j];
                    out[((size_t)n * 7 + v) * OE + o] = (s > 0.0f) ? s : expm1f(s);  // elu
                }
            }
        }
    }
}

// ================= launch =================
extern "C" void kernel_launch(void* const* d_in, const int* in_sizes, int n_in,
                              void* d_out, int out_size) {
    const float* h  = (const float*)d_in[0];   // (256,256,64,7)
    const float* W  = (const float*)d_in[1];   // (16384,256)
    const float* a  = (const float*)d_in[2];   // (512,1)
    const float* Bp = (const float*)d_in[3];   // (7,7)
    float* out = (float*)d_out;                // (256,7,256)

    cudaFuncSetAttribute(fused_kernel, cudaFuncAttributeMaxDynamicSharedMemorySize, SMEM_BYTES);
    fused_kernel<<<NCTA, 512, SMEM_BYTES>>>(h, W, a, Bp, out);
}

// round 10
// speedup vs baseline: 1.0155x; 1.0155x over previous
#include <cuda_runtime.h>
#include <cuda_fp16.h>

// ---------------- problem constants ----------------
#define V_N   7
#define NB    256
#define KTOT  16384      // C*T
#define OE    256
#define MTOT  1792       // NB * V_N
#define H_NSTR 114688    // C*T*V
#define H_CSTR 448       // T*V

// ---------------- GEMM tiling ----------------
#define MT    112        // M rows per CTA (= 16 batch rows exactly)
#define NPB   16         // batch rows per M-block
#define KTILE 64
#define NKT_TOTAL 256    // KTOT / KTILE (k64 chunks)
#define NSPLIT 9
#define NCTA   144       // 16 M-blocks x 9 K-splits

// SMEM stage layout
#define AS_NSTR 456                   // floats per n row (448 data + 8 pad)
#define AS_BYTES (NPB * AS_NSTR * 4)  // 29184
#define B_BYTES  (KTILE * OE * 2)     // 32768 (fp16)
#define STAGE_B  (AS_BYTES + B_BYTES) // 61952
#define NSTAGE   3
#define SMEM_BYTES (NSTAGE * STAGE_B) // 185856

// ---------------- device scratch ----------------
__device__ __half g_Wh[KTOT * OE];               // fp16 fragment/swizzled W^T (8.4 MB)
__device__ float  g_part[NSPLIT * MTOT * OE];    // K-split partial Wh (16.5 MB)
__device__ float  g_adjn[49];
__device__ unsigned g_flag[NKT_TOTAL];           // per-W-chunk ready flags (reset by tail)

// ---------------- helpers ----------------
__device__ __forceinline__ unsigned smem_u32(const void* p) {
    unsigned a;
    asm("{ .reg .u64 t; cvta.to.shared.u64 t, %1; cvt.u32.u64 %0, t; }" : "=r"(a) : "l"(p));
    return a;
}
__device__ __forceinline__ unsigned pk2h(float lo, float hi) {
    unsigned r;
    asm("cvt.rn.f16x2.f32 %0, %1, %2;" : "=r"(r) : "f"(hi), "f"(lo));
    return r;
}
#define CP_ASYNC_16(dst_u32, src) \
    asm volatile("cp.async.cg.shared.global [%0], [%1], 16;" :: "r"(dst_u32), "l"(src) : "memory")
#define CP_COMMIT() asm volatile("cp.async.commit_group;" ::: "memory")
#define CP_WAIT1()  asm volatile("cp.async.wait_group 1;" ::: "memory")

#define MMA_F16(c, A, B0, B1) \
    asm volatile("mma.sync.aligned.m16n8k16.row.col.f32.f16.f16.f32 " \
                 "{%0,%1,%2,%3},{%4,%5,%6,%7},{%8,%9},{%0,%1,%2,%3};\n" \
                 : "+f"(c[0]), "+f"(c[1]), "+f"(c[2]), "+f"(c[3]) \
                 : "r"(A[0]), "r"(A[1]), "r"(A[2]), "r"(A[3]), "r"(B0), "r"(B1))

// ================= kernel 1: per-CTA W-prep (flagged) + GEMM =================
// Uniform split: bid -> (mb = bid/9, sp = bid%9). sp<4: 29 tiles, else 28.
// CTA preps chunks {kt in its range : kt-start ≡ mb (mod 16)} then GEMMs, polling
// g_flag[kt] (acquire) before each cp.async of W chunk kt.
__global__ void __launch_bounds__(512, 1) prep_gemm_kernel(const float* __restrict__ h,
                                                           const float* __restrict__ W,
                                                           const float* __restrict__ Bp) {
    extern __shared__ float sm[];
    const unsigned smem_base = smem_u32(sm);
    const int tid = threadIdx.x;
    const int bid = blockIdx.x;

    const int mb = bid / NSPLIT, sp = bid - mb * NSPLIT;
    const int cnt   = (sp < 4) ? 29 : 28;
    const int start = (sp < 4) ? sp * 29 : sp * 28 + 4;
    const int m0 = mb * MT;
    const int n_first = mb * NPB;

    // ---- Phase 0: prep this group's W chunks (<=2) ----
    for (int kt = start + mb; kt < start + cnt; kt += 16) {
        const int sub = tid >> 8;                 // 0..1 -> which k32 sub-tile
        const int tile32 = kt * 2 + sub;
        const int c = tid & 255;
        const float* wp = W + (size_t)tile32 * 32 * OE + c;
        unsigned pk[16];
#pragma unroll
        for (int t4 = 0; t4 < 4; t4++) {
            float v0 = wp[(2 * t4 + 0)  * OE], v1 = wp[(2 * t4 + 1)  * OE];
            float v2 = wp[(2 * t4 + 8)  * OE], v3 = wp[(2 * t4 + 9)  * OE];
            float v4 = wp[(2 * t4 + 16) * OE], v5 = wp[(2 * t4 + 17) * OE];
            float v6 = wp[(2 * t4 + 24) * OE], v7 = wp[(2 * t4 + 25) * OE];
            unsigned p00 = pk2h(v0, v1), p01 = pk2h(v2, v3);
            unsigned p10 = pk2h(v4, v5), p11 = pk2h(v6, v7);
            if ((c >> 1) & 1) {
                pk[t4 * 4 + 0] = p10; pk[t4 * 4 + 1] = p11;
                pk[t4 * 4 + 2] = p00; pk[t4 * 4 + 3] = p01;
            } else {
                pk[t4 * 4 + 0] = p00; pk[t4 * 4 + 1] = p01;
                pk[t4 * 4 + 2] = p10; pk[t4 * 4 + 3] = p11;
            }
        }
        uint4* dst = (uint4*)g_Wh + (size_t)tile32 * 1024 + c * 4;
        dst[0] = make_uint4(pk[0],  pk[1],  pk[2],  pk[3]);
        dst[1] = make_uint4(pk[4],  pk[5],  pk[6],  pk[7]);
        dst[2] = make_uint4(pk[8],  pk[9],  pk[10], pk[11]);
        dst[3] = make_uint4(pk[12], pk[13], pk[14], pk[15]);

        __threadfence();
        __syncthreads();
        if (tid == 0)
            asm volatile("st.global.release.gpu.u32 [%0], %1;" :: "l"(&g_flag[kt]), "r"(1u) : "memory");
    }

    // adjacency normalization (any single thread; tail kernel reads it next launch-step)
    if (bid == NCTA - 1 && tid == 0) {
        float adj[49];
        float mn = 1e30f, mx = -1e30f;
        for (int k = 0; k < 49; k++) {
            float x = Bp[k] + 1e-6f + ((k / 7) == (k % 7) ? 1.0f : 0.0f);
            adj[k] = x;
            mn = fminf(mn, x);
            mx = fmaxf(mx, x);
        }
        float inv = 1.0f / (mx - mn);
        float dsum[7];
        for (int i2 = 0; i2 < 7; i2++) {
            float sum = 0.0f;
            for (int j = 0; j < 7; j++) {
                adj[i2 * 7 + j] = (adj[i2 * 7 + j] - mn) * inv;
                sum += adj[i2 * 7 + j];
            }
            dsum[i2] = sum;
        }
        for (int i2 = 0; i2 < 7; i2++) {
            float di = 1.0f / sqrtf(dsum[i2]);
            for (int j = 0; j < 7; j++)
                g_adjn[i2 * 7 + j] = adj[i2 * 7 + j] * di / sqrtf(dsum[j]);
        }
    }

    // ---- Phase 1: GEMM (R8 core) ----
    // staging slots: 1792 A float4 + 2048 B 16B-chunks = 3840
    int srcOff[8]; unsigned dstOff[8];
    bool isB[8], valid[8];
#pragma unroll
    for (int q = 0; q < 8; q++) {
        int f = tid + q * 512;
        valid[q] = (f < 3840);
        if (f < 1792) {
            int nr = f / 112, s4 = f - nr * 112;
            isB[q] = false;
            srcOff[q] = (n_first + nr) * H_NSTR + s4 * 4;
            dstOff[q] = (unsigned)(nr * AS_NSTR * 4 + s4 * 16);
        } else {
            int b = f - 1792;
            isB[q] = true;
            srcOff[q] = b * 8;
            dstOff[q] = (unsigned)(AS_BYTES + b * 16);
        }
    }

    // fragment geometry
    const int w = tid >> 5, lane = tid & 31;
    const int g = lane >> 2, t4 = lane & 3;
    const int nu = (w < 12) ? 2 : 1;
    const int un = w & 3;
    int um[2]; int baseA[2][2];
#pragma unroll
    for (int ui = 0; ui < 2; ui++) {
        int u = (ui == 0) ? w : (w + 16);
        um[ui] = u >> 2;
#pragma unroll
        for (int r = 0; r < 2; r++) {
            int m = um[ui] * 16 + g + r * 8;
            int nr = m / 7;
            baseA[ui][r] = nr * AS_NSTR + (m - nr * 7);
        }
    }
    const int xg = (g >> 1) & 1;
    const unsigned bThread = (unsigned)((un * 64 + g) * 64);

    float acc[2][8][4];
#pragma unroll
    for (int ui = 0; ui < 2; ui++)
#pragma unroll
        for (int nt = 0; nt < 8; nt++)
#pragma unroll
            for (int r = 0; r < 4; r++) acc[ui][nt][r] = 0.0f;

    auto issue = [&](int it, int buf) {
        const int kt = start + it;
        // wait for W chunk kt to be prepped (acquire)
        {
            unsigned v;
            for (;;) {
                asm volatile("ld.global.acquire.gpu.u32 %0, [%1];" : "=r"(v) : "l"(&g_flag[kt]) : "memory");
                if (v) break;
                __nanosleep(64);
            }
        }
        const unsigned sb = smem_base + (unsigned)(buf * STAGE_B);
        const float* ha = h + kt * H_CSTR;
        const __half* wb = g_Wh + (size_t)kt * 16384;
#pragma unroll
        for (int q = 0; q < 8; q++) {
            if (!valid[q]) continue;
            if (isB[q]) CP_ASYNC_16(sb + dstOff[q], wb + srcOff[q]);
            else        CP_ASYNC_16(sb + dstOff[q], ha + srcOff[q]);
        }
    };

    issue(0, 0); CP_COMMIT();
    issue(1, 1); CP_COMMIT();

    int buf = 0, buf2 = 2;
    for (int it = 0; it < cnt; ++it) {
        CP_WAIT1();
        __syncthreads();
        if (it + 2 < cnt) issue(it + 2, buf2);
        CP_COMMIT();

        const float* As = sm + buf * (STAGE_B / 4);
        const char*  Bs = (const char*)sm + buf * STAGE_B + AS_BYTES;

#pragma unroll
        for (int kg = 0; kg < 4; kg++) {
            const int ko = (kg * 16 + 2 * t4) * 7;
            unsigned afr[2][4];
            afr[0][0] = pk2h(As[baseA[0][0] + ko],      As[baseA[0][0] + ko + 7]);
            afr[0][1] = pk2h(As[baseA[0][1] + ko],      As[baseA[0][1] + ko + 7]);
            afr[0][2] = pk2h(As[baseA[0][0] + ko + 56], As[baseA[0][0] + ko + 63]);
            afr[0][3] = pk2h(As[baseA[0][1] + ko + 56], As[baseA[0][1] + ko + 63]);
            if (nu == 2) {
                afr[1][0] = pk2h(As[baseA[1][0] + ko],      As[baseA[1][0] + ko + 7]);
                afr[1][1] = pk2h(As[baseA[1][1] + ko],      As[baseA[1][1] + ko + 7]);
                afr[1][2] = pk2h(As[baseA[1][0] + ko + 56], As[baseA[1][0] + ko + 63]);
                afr[1][3] = pk2h(As[baseA[1][1] + ko + 56], As[baseA[1][1] + ko + 63]);
            }
            const char* bbase = Bs + (kg >> 1) * 16384 +
                                (unsigned)((((2 * t4 + (kg & 1)) ^ xg)) * 8) + bThread;
#pragma unroll
            for (int nt = 0; nt < 8; nt++) {
                uint2 b = *(const uint2*)(bbase + nt * 512);
                MMA_F16(acc[0][nt], afr[0], b.x, b.y);
                if (nu == 2) MMA_F16(acc[1][nt], afr[1], b.x, b.y);
            }
        }
        buf = (buf == 2) ? 0 : buf + 1;
        buf2 = (buf2 == 2) ? 0 : buf2 + 1;
    }

    // epilogue: write partials
    float* op = g_part + ((size_t)sp * MTOT + m0) * OE;
#pragma unroll
    for (int ui = 0; ui < 2; ui++) {
        if (ui >= nu) break;
#pragma unroll
        for (int nt = 0; nt < 8; nt++) {
            int r = um[ui] * 16 + g;
            int c = un * 64 + nt * 8 + 2 * t4;
            *(float2*)&op[(size_t)r * OE + c]       = make_float2(acc[ui][nt][0], acc[ui][nt][1]);
            *(float2*)&op[(size_t)(r + 8) * OE + c] = make_float2(acc[ui][nt][2], acc[ui][nt][3]);
        }
    }
}

// ================= tail: reset flags, reduce partials, attention, elu =================
__global__ void tail_kernel(const float* __restrict__ a, float* __restrict__ out) {
    __shared__ float red1[8][7], red2[8][7];
    __shared__ float s1s[7], s2s[7];
    __shared__ float adjn_s[49], att[49], att2[49];

    const int n = blockIdx.x;
    const int o = threadIdx.x;

    if (o == 0) g_flag[n] = 0;     // reset producer flags for next launch (256 blocks)

    float wh[7];
#pragma unroll
    for (int v = 0; v < 7; v++) {
        float s = 0.0f;
#pragma unroll
        for (int ksi = 0; ksi < NSPLIT; ksi++)
            s += g_part[((size_t)ksi * MTOT + n * 7 + v) * OE + o];
        wh[v] = s;
    }
    if (o < 49) adjn_s[o] = g_adjn[o];

    const float a1 = a[o];
    const float a2 = a[OE + o];
    const int wid = o >> 5, lane = o & 31;
#pragma unroll
    for (int v = 0; v < 7; v++) {
        float p1 = wh[v] * a1;
        float p2 = wh[v] * a2;
#pragma unroll
        for (int off = 16; off > 0; off >>= 1) {
            p1 += __shfl_down_sync(0xffffffffu, p1, off);
            p2 += __shfl_down_sync(0xffffffffu, p2, off);
        }
        if (lane == 0) { red1[wid][v] = p1; red2[wid][v] = p2; }
    }
    __syncthreads();
    if (o < 7) {
        float s = 0.0f;
        for (int w2 = 0; w2 < 8; w2++) s += red1[w2][o];
        s1s[o] = s;
    } else if (o >= 32 && o < 39) {
        float s = 0.0f;
        for (int w2 = 0; w2 < 8; w2++) s += red2[w2][o - 32];
        s2s[o - 32] = s;
    }
    __syncthreads();
    if (o < 7) {
        float e[7];
        float mx = -1e30f;
#pragma unroll
        for (int j = 0; j < 7; j++) {
            float x = s1s[o] + s2s[j];
            x = (x >= 0.0f) ? x : 0.2f * x;   // leaky_relu alpha=0.2
            e[j] = x;
            mx = fmaxf(mx, x);
        }
        float sum = 0.0f;
#pragma unroll
        for (int j = 0; j < 7; j++) { e[j] = expf(e[j] - mx); sum += e[j]; }
        float inv = 1.0f / sum;
#pragma unroll
        for (int j = 0; j < 7; j++) att[o * 7 + j] = e[j] * inv;
    }
    __syncthreads();
    if (o < 49) {
        int i = o / 7, kcol = o - i * 7;
        float s = 0.0f;
#pragma unroll
        for (int j = 0; j < 7; j++) s += adjn_s[i * 7 + j] * att[j * 7 + kcol];
        att2[o] = s;
    }
    __syncthreads();
#pragma unroll
    for (int v = 0; v < 7; v++) {
        float s = 0.0f;
#pragma unroll
        for (int j = 0; j < 7; j++) s += att2[v * 7 + j] * wh[j];
        out[((size_t)n * 7 + v) * OE + o] = (s > 0.0f) ? s : expm1f(s);  // elu
    }
}

// ================= launch =================
extern "C" void kernel_launch(void* const* d_in, const int* in_sizes, int n_in,
                              void* d_out, int out_size) {
    const float* h  = (const float*)d_in[0];   // (256,256,64,7)
    const float* W  = (const float*)d_in[1];   // (16384,256)
    const float* a  = (const float*)d_in[2];   // (512,1)
    const float* Bp = (const float*)d_in[3];   // (7,7)
    float* out = (float*)d_out;                // (256,7,256)

    cudaFuncSetAttribute(prep_gemm_kernel, cudaFuncAttributeMaxDynamicSharedMemorySize, SMEM_BYTES);
    prep_gemm_kernel<<<NCTA, 512, SMEM_BYTES>>>(h, W, Bp);

    tail_kernel<<<NB, OE>>>(a, out);
}

// round 11
// speedup vs baseline: 1.0443x; 1.0283x over previous
#include <cuda_runtime.h>
#include <cuda_fp16.h>

// ---------------- problem constants ----------------
#define V_N   7
#define NB    256
#define KTOT  16384      // C*T
#define OE    256
#define MTOT  1792       // NB * V_N
#define H_NSTR 114688    // C*T*V
#define H_CSTR 448       // T*V

// ---------------- GEMM tiling ----------------
#define MT    112        // M rows per CTA (= 16 batch rows exactly)
#define NPB   16         // batch rows per M-block
#define KTILE 64
#define NKT_TOTAL 256    // KTOT / KTILE
#define MAXSPLIT 10

// SMEM stage layout
#define AS_NSTR 456                   // floats per n row (448 data + 8 pad)
#define AS_BYTES (NPB * AS_NSTR * 4)  // 29184
#define B_BYTES  (KTILE * OE * 2)     // 32768 (fp16)
#define STAGE_B  (AS_BYTES + B_BYTES) // 61952
#define NSTAGE   3
#define SMEM_BYTES (NSTAGE * STAGE_B) // 185856

// ---------------- device scratch ----------------
__device__ __half g_Wh[KTOT * OE];               // fp16 fragment/swizzled W^T (8.4 MB)
__device__ float  g_part[MAXSPLIT * MTOT * OE];  // K-split partial Wh
__device__ float  g_adjn[49];

// ---------------- helpers ----------------
__device__ __forceinline__ unsigned smem_u32(const void* p) {
    unsigned a;
    asm("{ .reg .u64 t; cvta.to.shared.u64 t, %1; cvt.u32.u64 %0, t; }" : "=r"(a) : "l"(p));
    return a;
}
__device__ __forceinline__ unsigned pk2h(float lo, float hi) {
    unsigned r;
    asm("cvt.rn.f16x2.f32 %0, %1, %2;" : "=r"(r) : "f"(hi), "f"(lo));
    return r;
}
#define CP_ASYNC_16(dst_u32, src) \
    asm volatile("cp.async.cg.shared.global [%0], [%1], 16;" :: "r"(dst_u32), "l"(src) : "memory")
#define CP_COMMIT() asm volatile("cp.async.commit_group;" ::: "memory")
#define CP_WAIT1()  asm volatile("cp.async.wait_group 1;" ::: "memory")

#define MMA_F16(c, A, B0, B1) \
    asm volatile("mma.sync.aligned.m16n8k16.row.col.f32.f16.f16.f32 " \
                 "{%0,%1,%2,%3},{%4,%5,%6,%7},{%8,%9},{%0,%1,%2,%3};\n" \
                 : "+f"(c[0]), "+f"(c[1]), "+f"(c[2]), "+f"(c[3]) \
                 : "r"(A[0]), "r"(A[1]), "r"(A[2]), "r"(A[3]), "r"(B0), "r"(B1))

// ================= prep: W (f32) -> g_Wh (fp16, per-k32 swizzled frag layout) =============
// Task (tile, c): 32 independent coalesced LDG.32 of column c across the k32-tile's rows,
// pack 16 u32, store 4 contiguous uint4 (granules c*4 + 0..3). High MLP, no smem.
__global__ void __launch_bounds__(256) prep_kernel(const float* __restrict__ W,
                                                   const float* __restrict__ Bp) {
    const int id = blockIdx.x * 256 + threadIdx.x;    // 512 blocks -> 131072 tasks
    const int tile = id >> 8, c = id & 255;
    const float* wp = W + (size_t)tile * 32 * OE + c;
    unsigned pk[16];
#pragma unroll
    for (int t4 = 0; t4 < 4; t4++) {
        float v0 = wp[(2 * t4 + 0)  * OE], v1 = wp[(2 * t4 + 1)  * OE];
        float v2 = wp[(2 * t4 + 8)  * OE], v3 = wp[(2 * t4 + 9)  * OE];
        float v4 = wp[(2 * t4 + 16) * OE], v5 = wp[(2 * t4 + 17) * OE];
        float v6 = wp[(2 * t4 + 24) * OE], v7 = wp[(2 * t4 + 25) * OE];
        unsigned p00 = pk2h(v0, v1), p01 = pk2h(v2, v3);
        unsigned p10 = pk2h(v4, v5), p11 = pk2h(v6, v7);
        if ((c >> 1) & 1) {
            pk[t4 * 4 + 0] = p10; pk[t4 * 4 + 1] = p11;
            pk[t4 * 4 + 2] = p00; pk[t4 * 4 + 3] = p01;
        } else {
            pk[t4 * 4 + 0] = p00; pk[t4 * 4 + 1] = p01;
            pk[t4 * 4 + 2] = p10; pk[t4 * 4 + 3] = p11;
        }
    }
    uint4* dst = (uint4*)g_Wh + (size_t)tile * 1024 + c * 4;
    dst[0] = make_uint4(pk[0],  pk[1],  pk[2],  pk[3]);
    dst[1] = make_uint4(pk[4],  pk[5],  pk[6],  pk[7]);
    dst[2] = make_uint4(pk[8],  pk[9],  pk[10], pk[11]);
    dst[3] = make_uint4(pk[12], pk[13], pk[14], pk[15]);

    if (blockIdx.x == 0 && threadIdx.x == 0) {
        float adj[49];
        float mn = 1e30f, mx = -1e30f;
        for (int k = 0; k < 49; k++) {
            float x = Bp[k] + 1e-6f + ((k / 7) == (k % 7) ? 1.0f : 0.0f);
            adj[k] = x;
            mn = fminf(mn, x);
            mx = fmaxf(mx, x);
        }
        float inv = 1.0f / (mx - mn);
        float dsum[7];
        for (int i2 = 0; i2 < 7; i2++) {
            float sum = 0.0f;
            for (int j = 0; j < 7; j++) {
                adj[i2 * 7 + j] = (adj[i2 * 7 + j] - mn) * inv;
                sum += adj[i2 * 7 + j];
            }
            dsum[i2] = sum;
        }
        for (int i2 = 0; i2 < 7; i2++) {
            float di = 1.0f / sqrtf(dsum[i2]);
            for (int j = 0; j < 7; j++)
                g_adjn[i2 * 7 + j] = adj[i2 * 7 + j] * di / sqrtf(dsum[j]);
        }
    }
}

// ================= main GEMM: partial Wh = hf @ W (fp16 mma.sync, f32 accum) =============
// grid = 148 CTAs: first 4 M-blocks get 10 K-splits, last 12 get 9.
__global__ void __launch_bounds__(512, 1) gemm_kernel(const float* __restrict__ h) {
    extern __shared__ float sm[];
    const unsigned smem_base = smem_u32(sm);
    const int tid = threadIdx.x;
    const int bid = blockIdx.x;

    int mb, sp, s_cnt;
    if (bid < 40) { mb = bid / 10; sp = bid - mb * 10; s_cnt = 10; }
    else { int r = bid - 40; mb = 4 + r / 9; sp = r - (mb - 4) * 9; s_cnt = 9; }
    const int base_t = NKT_TOTAL / s_cnt, rem = NKT_TOTAL % s_cnt;
    const int cnt   = base_t + (sp < rem ? 1 : 0);
    const int start = sp * base_t + (sp < rem ? sp : rem);
    const int m0 = mb * MT;
    const int n_first = mb * NPB;

    // ---- staging slots: 1792 A float4 + 2048 B 16B-chunks = 3840 ----
    int srcOff[8]; unsigned dstOff[8];
    bool isB[8], valid[8];
#pragma unroll
    for (int q = 0; q < 8; q++) {
        int f = tid + q * 512;
        valid[q] = (f < 3840);
        if (f < 1792) {
            int nr = f / 112, s4 = f - nr * 112;
            isB[q] = false;
            srcOff[q] = (n_first + nr) * H_NSTR + s4 * 4;
            dstOff[q] = (unsigned)(nr * AS_NSTR * 4 + s4 * 16);
        } else {
            int b = f - 1792;
            isB[q] = true;
            srcOff[q] = b * 8;
            dstOff[q] = (unsigned)(AS_BYTES + b * 16);
        }
    }

    // ---- fragment geometry ----
    const int w = tid >> 5, lane = tid & 31;
    const int g = lane >> 2, t4 = lane & 3;
    const int nu = (w < 12) ? 2 : 1;
    const int un = w & 3;
    int um[2]; int baseA[2][2];
#pragma unroll
    for (int ui = 0; ui < 2; ui++) {
        int u = (ui == 0) ? w : (w + 16);
        um[ui] = u >> 2;
#pragma unroll
        for (int r = 0; r < 2; r++) {
            int m = um[ui] * 16 + g + r * 8;
            int nr = m / 7;
            baseA[ui][r] = nr * AS_NSTR + (m - nr * 7);
        }
    }
    const int xg = (g >> 1) & 1;
    const unsigned bThread = (unsigned)((un * 64 + g) * 64);

    float acc[2][8][4];
#pragma unroll
    for (int ui = 0; ui < 2; ui++)
#pragma unroll
        for (int nt = 0; nt < 8; nt++)
#pragma unroll
            for (int r = 0; r < 4; r++) acc[ui][nt][r] = 0.0f;

    auto issue = [&](int it, int buf) {
        const int kt = start + it;
        const unsigned sb = smem_base + (unsigned)(buf * STAGE_B);
        const float* ha = h + kt * H_CSTR;
        const __half* wb = g_Wh + (size_t)kt * 16384;
#pragma unroll
        for (int q = 0; q < 8; q++) {
            if (!valid[q]) continue;
            if (isB[q]) CP_ASYNC_16(sb + dstOff[q], wb + srcOff[q]);
            else        CP_ASYNC_16(sb + dstOff[q], ha + srcOff[q]);
        }
    };

    issue(0, 0); CP_COMMIT();
    issue(1, 1); CP_COMMIT();

    int buf = 0, buf2 = 2;
    for (int it = 0; it < cnt; ++it) {
        CP_WAIT1();
        __syncthreads();
        if (it + 2 < cnt) issue(it + 2, buf2);
        CP_COMMIT();

        const float* As = sm + buf * (STAGE_B / 4);
        const char*  Bs = (const char*)sm + buf * STAGE_B + AS_BYTES;

#pragma unroll
        for (int kg = 0; kg < 4; kg++) {
            const int ko = (kg * 16 + 2 * t4) * 7;
            unsigned afr[2][4];
            afr[0][0] = pk2h(As[baseA[0][0] + ko],      As[baseA[0][0] + ko + 7]);
            afr[0][1] = pk2h(As[baseA[0][1] + ko],      As[baseA[0][1] + ko + 7]);
            afr[0][2] = pk2h(As[baseA[0][0] + ko + 56], As[baseA[0][0] + ko + 63]);
            afr[0][3] = pk2h(As[baseA[0][1] + ko + 56], As[baseA[0][1] + ko + 63]);
            if (nu == 2) {
                afr[1][0] = pk2h(As[baseA[1][0] + ko],      As[baseA[1][0] + ko + 7]);
                afr[1][1] = pk2h(As[baseA[1][1] + ko],      As[baseA[1][1] + ko + 7]);
                afr[1][2] = pk2h(As[baseA[1][0] + ko + 56], As[baseA[1][0] + ko + 63]);
                afr[1][3] = pk2h(As[baseA[1][1] + ko + 56], As[baseA[1][1] + ko + 63]);
            }
            const char* bbase = Bs + (kg >> 1) * 16384 +
                                (unsigned)((((2 * t4 + (kg & 1)) ^ xg)) * 8) + bThread;
#pragma unroll
            for (int nt = 0; nt < 8; nt++) {
                uint2 b = *(const uint2*)(bbase + nt * 512);
                MMA_F16(acc[0][nt], afr[0], b.x, b.y);
                if (nu == 2) MMA_F16(acc[1][nt], afr[1], b.x, b.y);
            }
        }
        buf = (buf == 2) ? 0 : buf + 1;
        buf2 = (buf2 == 2) ? 0 : buf2 + 1;
    }

    // ---- epilogue ----
    float* op = g_part + ((size_t)sp * MTOT + m0) * OE;
#pragma unroll
    for (int ui = 0; ui < 2; ui++) {
        if (ui >= nu) break;
#pragma unroll
        for (int nt = 0; nt < 8; nt++) {
            int r = um[ui] * 16 + g;
            int c = un * 64 + nt * 8 + 2 * t4;
            *(float2*)&op[(size_t)r * OE + c]       = make_float2(acc[ui][nt][0], acc[ui][nt][1]);
            *(float2*)&op[(size_t)(r + 8) * OE + c] = make_float2(acc[ui][nt][2], acc[ui][nt][3]);
        }
    }
}

// ================= tail: 2 n's per 512-thread block, MLP-friendly reduction ============
__global__ void __launch_bounds__(512) tail_kernel(const float* __restrict__ a,
                                                   float* __restrict__ out) {
    __shared__ float red1[2][8][7], red2[2][8][7];
    __shared__ float s1s[2][7], s2s[2][7];
    __shared__ float adjn_s[49], att[2][49], att2[2][49];

    const int tid = threadIdx.x;
    const int hh = tid >> 8;               // half-block index (0/1)
    const int o  = tid & 255;
    const int n  = blockIdx.x * 2 + hh;    // grid = 128
    const int s_cnt = ((n >> 4) < 4) ? 10 : 9;

    // ksi-outer, 7 independent loads per iteration -> MLP >= 7/thread
    float wh[7];
#pragma unroll
    for (int v = 0; v < 7; v++) wh[v] = 0.0f;
    for (int ksi = 0; ksi < s_cnt; ksi++) {
        const float* p = &g_part[((size_t)ksi * MTOT + n * 7) * OE + o];
#pragma unroll
        for (int v = 0; v < 7; v++) wh[v] += __ldg(p + v * OE);
    }
    if (tid < 49) adjn_s[tid] = g_adjn[tid];

    const float a1 = __ldg(&a[o]);
    const float a2 = __ldg(&a[OE + o]);
    const int wid = o >> 5, lane = o & 31;
#pragma unroll
    for (int v = 0; v < 7; v++) {
        float p1 = wh[v] * a1;
        float p2 = wh[v] * a2;
#pragma unroll
        for (int off = 16; off > 0; off >>= 1) {
            p1 += __shfl_down_sync(0xffffffffu, p1, off);
            p2 += __shfl_down_sync(0xffffffffu, p2, off);
        }
        if (lane == 0) { red1[hh][wid][v] = p1; red2[hh][wid][v] = p2; }
    }
    __syncthreads();
    if (o < 7) {
        float s = 0.0f;
        for (int w2 = 0; w2 < 8; w2++) s += red1[hh][w2][o];
        s1s[hh][o] = s;
    } else if (o >= 32 && o < 39) {
        float s = 0.0f;
        for (int w2 = 0; w2 < 8; w2++) s += red2[hh][w2][o - 32];
        s2s[hh][o - 32] = s;
    }
    __syncthreads();
    if (o < 7) {
        float e[7];
        float mx = -1e30f;
#pragma unroll
        for (int j = 0; j < 7; j++) {
            float x = s1s[hh][o] + s2s[hh][j];
            x = (x >= 0.0f) ? x : 0.2f * x;   // leaky_relu alpha=0.2
            e[j] = x;
            mx = fmaxf(mx, x);
        }
        float sum = 0.0f;
#pragma unroll
        for (int j = 0; j < 7; j++) { e[j] = expf(e[j] - mx); sum += e[j]; }
        float inv = 1.0f / sum;
#pragma unroll
        for (int j = 0; j < 7; j++) att[hh][o * 7 + j] = e[j] * inv;
    }
    __syncthreads();
    if (o < 49) {
        int i = o / 7, kcol = o - i * 7;
        float s = 0.0f;
#pragma unroll
        for (int j = 0; j < 7; j++) s += adjn_s[i * 7 + j] * att[hh][j * 7 + kcol];
        att2[hh][o] = s;
    }
    __syncthreads();
#pragma unroll
    for (int v = 0; v < 7; v++) {
        float s = 0.0f;
#pragma unroll
        for (int j = 0; j < 7; j++) s += att2[hh][v * 7 + j] * wh[j];
        out[((size_t)n * 7 + v) * OE + o] = (s > 0.0f) ? s : expm1f(s);  // elu
    }
}

// ================= launch =================
extern "C" void kernel_launch(void* const* d_in, const int* in_sizes, int n_in,
                              void* d_out, int out_size) {
    const float* h  = (const float*)d_in[0];   // (256,256,64,7)
    const float* W  = (const float*)d_in[1];   // (16384,256)
    const float* a  = (const float*)d_in[2];   // (512,1)
    const float* Bp = (const float*)d_in[3];   // (7,7)
    float* out = (float*)d_out;                // (256,7,256)

    prep_kernel<<<512, 256>>>(W, Bp);

    cudaFuncSetAttribute(gemm_kernel, cudaFuncAttributeMaxDynamicSharedMemorySize, SMEM_BYTES);
    gemm_kernel<<<148, 512, SMEM_BYTES>>>(h);

    tail_kernel<<<NB / 2, 512>>>(a, out);
}